// round 2
// baseline (speedup 1.0000x reference)
#include <cuda_runtime.h>
#include <stdint.h>
#include <math.h>

#define NB 256
#define TOK (NB*64)

__device__ float g_W[1024*1024];       // fused weight: rows=input dim (h:0-511, z:512-1023), cols: 0-511 logits-proj, 512-1023 value-proj
__device__ float g_PV[(size_t)TOK*1024];

__device__ __forceinline__ float to_tf32(float x){ float r; asm("cvt.rna.tf32.f32 %0, %1;" : "=f"(r) : "f"(x)); return r; }
__device__ __forceinline__ uint32_t fb(float x){ return __float_as_uint(x); }
__device__ __forceinline__ void mma8(float* c, const uint32_t* a, const uint32_t* b){
    asm volatile("mma.sync.aligned.m16n8k8.row.col.f32.tf32.tf32.f32 "
        "{%0,%1,%2,%3}, {%4,%5,%6,%7}, {%8,%9}, {%0,%1,%2,%3};"
        : "+f"(c[0]), "+f"(c[1]), "+f"(c[2]), "+f"(c[3])
        : "r"(a[0]), "r"(a[1]), "r"(a[2]), "r"(a[3]), "r"(b[0]), "r"(b[1]));
}
__device__ __forceinline__ float wmax(float v){
    #pragma unroll
    for (int o=16;o>0;o>>=1) v = fmaxf(v, __shfl_xor_sync(0xffffffffu,v,o));
    return v;
}
__device__ __forceinline__ float wsum(float v){
    #pragma unroll
    for (int o=16;o>0;o>>=1) v += __shfl_xor_sync(0xffffffffu,v,o);
    return v;
}

// ============================================================
// K1: fused weight precompute, fp32 SIMT. grid (8,8,4), 256 thr
// C[m,n] = sum_k Aop[k,m] * Bop[k,n]  (K=1024, out 512x512 per quad)
// ============================================================
__global__ __launch_bounds__(256,4) void k_fuse(
    const float* __restrict__ Whk, const float* __restrict__ Whv,
    const float* __restrict__ Wzk, const float* __restrict__ Wzv,
    const float* __restrict__ Wq,  const float* __restrict__ Wo)
{
    __shared__ float sA[16][68], sB[16][68];
    const int quad = blockIdx.z;
    const float *Ap, *Bp; int row0, col0, bt; float scale;
    const float s = 0.04419417382415922f; // 1/sqrt(512)
    if (quad==0){ Ap=Whk; Bp=Wq;          row0=0;   col0=0;   bt=0; scale=s; }
    else if (quad==1){ Ap=Wzk; Bp=Wq+1024*512; row0=512; col0=0; bt=0; scale=s; }
    else if (quad==2){ Ap=Whv; Bp=Wo;     row0=0;   col0=512; bt=1; scale=1.f; }
    else      { Ap=Wzv; Bp=Wo+1024;       row0=512; col0=512; bt=1; scale=1.f; }

    const int tid = threadIdx.x;
    const int m0 = blockIdx.y*64, n0 = blockIdx.x*64;
    const int lr = tid>>4, lc4 = (tid&15)*4;
    const int tm = (tid>>4)*4, tn = (tid&15)*4;
    float acc[4][4];
    #pragma unroll
    for (int i=0;i<4;i++)
        #pragma unroll
        for (int j=0;j<4;j++) acc[i][j]=0.f;

    for (int kc=0; kc<1024; kc+=16){
        *(float4*)&sA[lr][lc4] = *(const float4*)(Ap + (size_t)(kc+lr)*512 + m0 + lc4);
        if (!bt){
            *(float4*)&sB[lr][lc4] = *(const float4*)(Bp + (size_t)(kc+lr)*512 + n0 + lc4);
        } else {
            int n = tid>>2, k4 = (tid&3)*4;
            float4 bv = *(const float4*)(Bp + (size_t)(n0+n)*2048 + kc + k4);
            sB[k4+0][n]=bv.x; sB[k4+1][n]=bv.y; sB[k4+2][n]=bv.z; sB[k4+3][n]=bv.w;
        }
        __syncthreads();
        #pragma unroll
        for (int kk=0;kk<16;kk++){
            float4 a = *(const float4*)&sA[kk][tm];
            float4 b = *(const float4*)&sB[kk][tn];
            float av[4]={a.x,a.y,a.z,a.w}, bv[4]={b.x,b.y,b.z,b.w};
            #pragma unroll
            for (int i=0;i<4;i++)
                #pragma unroll
                for (int j=0;j<4;j++) acc[i][j] += av[i]*bv[j];
        }
        __syncthreads();
    }
    #pragma unroll
    for (int i=0;i<4;i++){
        int m = row0 + m0 + tm + i;
        #pragma unroll
        for (int j=0;j<4;j++)
            g_W[(size_t)m*1024 + col0 + n0 + tn + j] = scale*acc[i][j];
    }
}

// ============================================================
// K2: PV = [h|z] @ W  (M=16384,N=1024,K=1024), tf32 mma.
// CTA 128x128, 256 thr, warps 2m x 4n, warp tile 64x32.
// ============================================================
__global__ __launch_bounds__(256,1) void k_pv(
    const float* __restrict__ h, const float* __restrict__ z)
{
    __shared__ float sA[128*36];   // [m][k]
    __shared__ float sB[32*136];   // [k][n]
    const int tid = threadIdx.x, lane = tid&31, wid = tid>>5;
    const int mwarp = (wid>>2)*64, nwarp = (wid&3)*32;
    const int m0 = blockIdx.y*128, n0 = blockIdx.x*128;

    float acc[4][4][4];
    #pragma unroll
    for (int a=0;a<4;a++)
        #pragma unroll
        for (int b=0;b<4;b++)
            #pragma unroll
            for (int c=0;c<4;c++) acc[a][b][c]=0.f;

    for (int kc=0; kc<1024; kc+=32){
        const float* X = (kc<512) ? h : z;
        const int kb = kc & 511;
        #pragma unroll
        for (int i=0;i<4;i++){
            int idx = tid + i*256;
            int m = idx>>3, kq = (idx&7)*4;
            float4 v = *(const float4*)(X + (size_t)(m0+m)*512 + kb + kq);
            sA[m*36+kq+0]=to_tf32(v.x); sA[m*36+kq+1]=to_tf32(v.y);
            sA[m*36+kq+2]=to_tf32(v.z); sA[m*36+kq+3]=to_tf32(v.w);
        }
        #pragma unroll
        for (int i=0;i<4;i++){
            int idx = tid + i*256;
            int k = idx>>5, nq = (idx&31)*4;
            float4 v = *(const float4*)(&g_W[(size_t)(kc+k)*1024 + n0 + nq]);
            sB[k*136+nq+0]=to_tf32(v.x); sB[k*136+nq+1]=to_tf32(v.y);
            sB[k*136+nq+2]=to_tf32(v.z); sB[k*136+nq+3]=to_tf32(v.w);
        }
        __syncthreads();
        #pragma unroll
        for (int kk=0;kk<32;kk+=8){
            uint32_t ua[4][4], ub[4][2];
            const int kr0 = kk + (lane&3), kr1 = kr0 + 4;
            #pragma unroll
            for (int ms=0;ms<4;ms++){
                int am = mwarp + ms*16 + (lane>>2);
                ua[ms][0]=fb(sA[am*36+kr0]);      ua[ms][1]=fb(sA[(am+8)*36+kr0]);
                ua[ms][2]=fb(sA[am*36+kr1]);      ua[ms][3]=fb(sA[(am+8)*36+kr1]);
            }
            #pragma unroll
            for (int ns=0;ns<4;ns++){
                int bn = nwarp + ns*8 + (lane>>2);
                ub[ns][0]=fb(sB[kr0*136+bn]);     ub[ns][1]=fb(sB[kr1*136+bn]);
            }
            #pragma unroll
            for (int ms=0;ms<4;ms++)
                #pragma unroll
                for (int ns=0;ns<4;ns++)
                    mma8(acc[ms][ns], ua[ms], ub[ns]);
        }
        __syncthreads();
    }
    #pragma unroll
    for (int ms=0;ms<4;ms++){
        int m = m0 + mwarp + ms*16 + (lane>>2);
        #pragma unroll
        for (int ns=0;ns<4;ns++){
            int n = n0 + nwarp + ns*8 + (lane&3)*2;
            g_PV[(size_t)m*1024 + n]     = acc[ms][ns][0];
            g_PV[(size_t)m*1024 + n + 1] = acc[ms][ns][1];
            g_PV[(size_t)(m+8)*1024 + n]     = acc[ms][ns][2];
            g_PV[(size_t)(m+8)*1024 + n + 1] = acc[ms][ns][3];
        }
    }
}

// ============================================================
// K3: per-batch attention + layernorm. grid 256, 512 thr.
// smem: hs[64][516], ls[64][65], ps[4096], qs[4096], mean[64], rstd[64]
// ============================================================
#define HS_STRIDE 516
#define SMEM3_FLOATS (64*HS_STRIDE + 64*65 + 4096 + 4096 + 128)

extern __shared__ float sm3[];

__global__ __launch_bounds__(512,1) void k_attn(
    const float* __restrict__ h, const float* __restrict__ lng,
    const float* __restrict__ lnb, float* __restrict__ out)
{
    float* hs = sm3;
    float* ls = hs + 64*HS_STRIDE;
    float* ps = ls + 64*65;
    float* qs = ps + 4096;
    float* mean_s = qs + 4096;
    float* rstd_s = mean_s + 64;

    const int b = blockIdx.x;
    const int tid = threadIdx.x, lane = tid&31, wid = tid>>5;
    const float* Pb = g_PV + (size_t)b*64*1024;

    // Phase A: h batch -> smem
    #pragma unroll
    for (int it=0; it<16; it++){
        int idx = tid + it*512;
        int r = idx>>7, c4 = (idx&127)*4;
        *(float4*)&hs[r*HS_STRIDE + c4] = *(const float4*)(h + ((size_t)b*64 + r)*512 + c4);
    }
    __syncthreads();

    // Phase B: logits = P @ h^T  (each thread: 2 k-rows x 4 q-cols)
    {
        const int k0 = (tid>>4)*2, q4 = tid&15;
        float la[2][4];
        #pragma unroll
        for (int i=0;i<2;i++)
            #pragma unroll
            for (int j=0;j<4;j++) la[i][j]=0.f;
        for (int d=0; d<512; d+=4){
            float4 p0 = *(const float4*)(Pb + (size_t)k0*1024 + d);
            float4 p1 = *(const float4*)(Pb + (size_t)(k0+1)*1024 + d);
            #pragma unroll
            for (int j=0;j<4;j++){
                float4 hv = *(const float4*)&hs[(q4 + j*16)*HS_STRIDE + d];
                la[0][j] += p0.x*hv.x + p0.y*hv.y + p0.z*hv.z + p0.w*hv.w;
                la[1][j] += p1.x*hv.x + p1.y*hv.y + p1.z*hv.z + p1.w*hv.w;
            }
        }
        #pragma unroll
        for (int j=0;j<4;j++){
            ls[k0*65 + q4 + j*16]     = la[0][j];
            ls[(k0+1)*65 + q4 + j*16] = la[1][j];
        }
    }
    __syncthreads();

    // Phase C: softmax over q per k-row (16 warps x 4 rows)
    #pragma unroll
    for (int i=0;i<4;i++){
        int r = wid*4 + i;
        float v0 = ls[r*65 + lane], v1 = ls[r*65 + lane + 32];
        float m = wmax(fmaxf(v0, v1));
        float e0 = __expf(v0 - m), e1 = __expf(v1 - m);
        float inv = 1.f / wsum(e0 + e1);
        ls[r*65 + lane] = e0*inv;
        ls[r*65 + lane + 32] = e1*inv;
    }
    __syncthreads();

    // Phase D: V' batch -> hs (overwrite)
    #pragma unroll
    for (int it=0; it<16; it++){
        int idx = tid + it*512;
        int r = idx>>7, c4 = (idx&127)*4;
        *(float4*)&hs[r*HS_STRIDE + c4] = *(const float4*)(Pb + (size_t)r*1024 + 512 + c4);
    }
    __syncthreads();

    // Phase E: O = probs @ V'   (thread: 8 k-rows x 8 d-cols)
    const int kg = tid>>6, dg = tid&63;
    float o[8][8];
    #pragma unroll
    for (int i=0;i<8;i++)
        #pragma unroll
        for (int j=0;j<8;j++) o[i][j]=0.f;
    for (int q=0; q<64; q++){
        float pr[8];
        #pragma unroll
        for (int i=0;i<8;i++) pr[i] = ls[(kg*8+i)*65 + q];
        float4 v0 = *(const float4*)&hs[q*HS_STRIDE + dg*8];
        float4 v1 = *(const float4*)&hs[q*HS_STRIDE + dg*8 + 4];
        #pragma unroll
        for (int i=0;i<8;i++){
            o[i][0] += pr[i]*v0.x; o[i][1] += pr[i]*v0.y;
            o[i][2] += pr[i]*v0.z; o[i][3] += pr[i]*v0.w;
            o[i][4] += pr[i]*v1.x; o[i][5] += pr[i]*v1.y;
            o[i][6] += pr[i]*v1.z; o[i][7] += pr[i]*v1.w;
        }
    }

    // Phase F: layernorm partials + reduce + write
    #pragma unroll
    for (int i=0;i<8;i++){
        float s1=0.f, s2=0.f;
        #pragma unroll
        for (int j=0;j<8;j++){ s1 += o[i][j]; s2 += o[i][j]*o[i][j]; }
        ps[(kg*8+i)*64 + dg] = s1;
        qs[(kg*8+i)*64 + dg] = s2;
    }
    __syncthreads();
    if (tid < 64){
        float s1=0.f, s2=0.f;
        #pragma unroll 8
        for (int g2=0; g2<64; g2++){ s1 += ps[tid*64+g2]; s2 += qs[tid*64+g2]; }
        float mu = s1 * (1.f/512.f);
        float var = s2 * (1.f/512.f) - mu*mu;
        mean_s[tid] = mu;
        rstd_s[tid] = rsqrtf(var + 1e-5f);
    }
    __syncthreads();
    float4 g0 = *(const float4*)(lng + dg*8), g1 = *(const float4*)(lng + dg*8 + 4);
    float4 b0 = *(const float4*)(lnb + dg*8), b1 = *(const float4*)(lnb + dg*8 + 4);
    #pragma unroll
    for (int i=0;i<8;i++){
        int k = kg*8 + i;
        float mu = mean_s[k], rs = rstd_s[k];
        float4 o0, o1;
        o0.x = (o[i][0]-mu)*rs*g0.x + b0.x;  o0.y = (o[i][1]-mu)*rs*g0.y + b0.y;
        o0.z = (o[i][2]-mu)*rs*g0.z + b0.z;  o0.w = (o[i][3]-mu)*rs*g0.w + b0.w;
        o1.x = (o[i][4]-mu)*rs*g1.x + b1.x;  o1.y = (o[i][5]-mu)*rs*g1.y + b1.y;
        o1.z = (o[i][6]-mu)*rs*g1.z + b1.z;  o1.w = (o[i][7]-mu)*rs*g1.w + b1.w;
        float* op = out + ((size_t)b*64 + k)*512 + dg*8;
        *(float4*)op = o0;
        *(float4*)(op+4) = o1;
    }
}

extern "C" void kernel_launch(void* const* d_in, const int* in_sizes, int n_in,
                              void* d_out, int out_size) {
    const float* h   = (const float*)d_in[0];
    const float* z   = (const float*)d_in[1];
    const float* Whk = (const float*)d_in[2];
    const float* Whv = (const float*)d_in[3];
    const float* Wzk = (const float*)d_in[4];
    const float* Wzv = (const float*)d_in[5];
    const float* Wq  = (const float*)d_in[6];
    const float* Wo  = (const float*)d_in[7];
    const float* lng = (const float*)d_in[8];
    const float* lnb = (const float*)d_in[9];
    float* out = (float*)d_out;

    static int inited = 0;
    if (!inited){
        cudaFuncSetAttribute(k_attn, cudaFuncAttributeMaxDynamicSharedMemorySize,
                             SMEM3_FLOATS*(int)sizeof(float));
        inited = 1;
    }

    k_fuse<<<dim3(8,8,4), 256>>>(Whk, Whv, Wzk, Wzv, Wq, Wo);
    k_pv<<<dim3(8,128), 256>>>(h, z);
    k_attn<<<256, 512, SMEM3_FLOATS*sizeof(float)>>>(h, lng, lnb, out);
}

// round 4
// speedup vs baseline: 1.2039x; 1.2039x over previous
#include <cuda_runtime.h>
#include <stdint.h>
#include <math.h>

#define NB 256
#define TOK (NB*64)

// g_W[k*1024 + n]: k = input dim (0-511 h, 512-1023 z); n = output (0-511 logits-proj scaled, 512-1023 value-proj)
// stored pre-rounded to tf32 (rna)
__device__ float g_W[1024*1024];
__device__ float g_PV[(size_t)TOK*1024];

__device__ __forceinline__ float to_tf32(float x){ float r; asm("cvt.rna.tf32.f32 %0, %1;" : "=f"(r) : "f"(x)); return r; }
__device__ __forceinline__ uint32_t fb(float x){ return __float_as_uint(x); }
__device__ __forceinline__ void mma8(float* c, const uint32_t* a, const uint32_t* b){
    asm volatile("mma.sync.aligned.m16n8k8.row.col.f32.tf32.tf32.f32 "
        "{%0,%1,%2,%3}, {%4,%5,%6,%7}, {%8,%9}, {%0,%1,%2,%3};"
        : "+f"(c[0]), "+f"(c[1]), "+f"(c[2]), "+f"(c[3])
        : "r"(a[0]), "r"(a[1]), "r"(a[2]), "r"(a[3]), "r"(b[0]), "r"(b[1]));
}
__device__ __forceinline__ float wmax(float v){
    #pragma unroll
    for (int o=16;o>0;o>>=1) v = fmaxf(v, __shfl_xor_sync(0xffffffffu,v,o));
    return v;
}
__device__ __forceinline__ float wsum(float v){
    #pragma unroll
    for (int o=16;o>0;o>>=1) v += __shfl_xor_sync(0xffffffffu,v,o);
    return v;
}
__device__ __forceinline__ uint32_t smem_u32(const void* p){
    uint32_t a; asm("{ .reg .u64 t; cvta.to.shared.u64 t, %1; cvt.u32.u64 %0, t; }" : "=r"(a) : "l"(p));
    return a;
}
__device__ __forceinline__ void cpa16(uint32_t dst, const void* src){
    asm volatile("cp.async.cg.shared.global [%0], [%1], 16;" :: "r"(dst), "l"(src) : "memory");
}
__device__ __forceinline__ void cpa_commit(){ asm volatile("cp.async.commit_group;" ::: "memory"); }

// ============================================================
// K1: fused weight precompute, fp32 SIMT, 512 threads.
// grid (8,8,4). Output stored pre-rounded to tf32.
// ============================================================
__global__ __launch_bounds__(512,2) void k_fuse(
    const float* __restrict__ Whk, const float* __restrict__ Whv,
    const float* __restrict__ Wzk, const float* __restrict__ Wzv,
    const float* __restrict__ Wq,  const float* __restrict__ Wo)
{
    __shared__ float sA[16][68], sB[16][68];
    const int quad = blockIdx.z;
    const float *Ap, *Bp; int row0, col0, bt; float scale;
    const float s = 0.04419417382415922f; // 1/sqrt(512)
    if (quad==0){ Ap=Whk; Bp=Wq;          row0=0;   col0=0;   bt=0; scale=s; }
    else if (quad==1){ Ap=Wzk; Bp=Wq+1024*512; row0=512; col0=0; bt=0; scale=s; }
    else if (quad==2){ Ap=Whv; Bp=Wo;     row0=0;   col0=512; bt=1; scale=1.f; }
    else      { Ap=Wzv; Bp=Wo+1024;       row0=512; col0=512; bt=1; scale=1.f; }

    const int tid = threadIdx.x;
    const int m0 = blockIdx.y*64, n0 = blockIdx.x*64;
    const int tm = (tid>>5)*4;        // 16 groups * 4 rows = 64
    const int tn = (tid&31)*2;        // 32 * 2 cols = 64
    float acc[4][2];
    #pragma unroll
    for (int i=0;i<4;i++){ acc[i][0]=0.f; acc[i][1]=0.f; }

    for (int kc=0; kc<1024; kc+=16){
        if (tid < 256){
            const int lr = tid>>4, lc4 = (tid&15)*4;
            *(float4*)&sA[lr][lc4] = *(const float4*)(Ap + (size_t)(kc+lr)*512 + m0 + lc4);
            if (!bt){
                *(float4*)&sB[lr][lc4] = *(const float4*)(Bp + (size_t)(kc+lr)*512 + n0 + lc4);
            } else {
                int n = tid>>2, k4 = (tid&3)*4;
                float4 bv = *(const float4*)(Bp + (size_t)(n0+n)*2048 + kc + k4);
                sB[k4+0][n]=bv.x; sB[k4+1][n]=bv.y; sB[k4+2][n]=bv.z; sB[k4+3][n]=bv.w;
            }
        }
        __syncthreads();
        #pragma unroll
        for (int kk=0;kk<16;kk++){
            float4 a = *(const float4*)&sA[kk][tm];
            float2 b = *(const float2*)&sB[kk][tn];
            acc[0][0] += a.x*b.x; acc[0][1] += a.x*b.y;
            acc[1][0] += a.y*b.x; acc[1][1] += a.y*b.y;
            acc[2][0] += a.z*b.x; acc[2][1] += a.z*b.y;
            acc[3][0] += a.w*b.x; acc[3][1] += a.w*b.y;
        }
        __syncthreads();
    }
    #pragma unroll
    for (int i=0;i<4;i++){
        int k = row0 + m0 + tm + i;       // input-dim index
        int n = col0 + n0 + tn;           // output index
        float2 v;
        v.x = to_tf32(scale*acc[i][0]);
        v.y = to_tf32(scale*acc[i][1]);
        *(float2*)&g_W[(size_t)k*1024 + n] = v;
    }
}

// ============================================================
// K2: PV = [h|z] @ W  (M=16384,N=1024,K=1024), tf32 mma.sync
// CTA 128x128, 256 thr (warps 2m x 4n, warp tile 64x32),
// 3-stage cp.async pipeline, K-chunk 32.
// smem per stage: A[128][36] + B[32][136] floats = 35840 B.
// ============================================================
#define KPV_STAGE_FLOATS (128*36 + 32*136)
#define KPV_SMEM_BYTES   (3*KPV_STAGE_FLOATS*4)

extern __shared__ float pvsm[];

__global__ __launch_bounds__(256,2) void k_pv(
    const float* __restrict__ h, const float* __restrict__ z)
{
    const int tid = threadIdx.x, lane = tid&31, wid = tid>>5;
    const int m0 = blockIdx.y*128, n0 = blockIdx.x*128;
    const int wm = (wid>>2)*64, wn = (wid&3)*32;

    float* stA[3]; float* stB[3];
    #pragma unroll
    for (int ss=0;ss<3;ss++){ stA[ss] = pvsm + ss*KPV_STAGE_FLOATS; stB[ss] = stA[ss] + 128*36; }

    float acc[4][4][4];
    #pragma unroll
    for (int a=0;a<4;a++)
        #pragma unroll
        for (int b=0;b<4;b++)
            #pragma unroll
            for (int c=0;c<4;c++) acc[a][b][c]=0.f;

    auto fill = [&](int c){
        const int sidx = c%3;
        const float* X = (c<16) ? h : z;
        const int kb = (c&15)*32;
        const int kc = c*32;
        float* A = stA[sidx]; float* B = stB[sidx];
        #pragma unroll
        for (int i=0;i<4;i++){
            int u = tid + 256*i;
            int m = u>>3, k4 = (u&7)*4;
            cpa16(smem_u32(A + m*36 + k4), X + (size_t)(m0+m)*512 + kb + k4);
        }
        #pragma unroll
        for (int i=0;i<4;i++){
            int u = tid + 256*i;
            int k = u>>5, n4 = (u&31)*4;
            cpa16(smem_u32(B + k*136 + n4), g_W + (size_t)(kc+k)*1024 + n0 + n4);
        }
        cpa_commit();
    };

    fill(0); fill(1);

    for (int c = 0; c < 32; c++){
        if (c < 31) asm volatile("cp.async.wait_group 1;" ::: "memory");
        else        asm volatile("cp.async.wait_group 0;" ::: "memory");
        __syncthreads();
        if (c < 30) fill(c+2);

        const float* A = stA[c%3];
        const float* B = stB[c%3];
        #pragma unroll
        for (int ks=0; ks<4; ks++){
            const int k0 = ks*8 + (lane&3);
            uint32_t af[4][4], bf[4][2];
            #pragma unroll
            for (int mf=0; mf<4; mf++){
                int r = wm + mf*16 + (lane>>2);
                af[mf][0] = fb(to_tf32(A[r*36 + k0]));
                af[mf][1] = fb(to_tf32(A[(r+8)*36 + k0]));
                af[mf][2] = fb(to_tf32(A[r*36 + k0 + 4]));
                af[mf][3] = fb(to_tf32(A[(r+8)*36 + k0 + 4]));
            }
            #pragma unroll
            for (int nf=0; nf<4; nf++){
                int cn = wn + nf*8 + (lane>>2);
                bf[nf][0] = fb(B[k0*136 + cn]);
                bf[nf][1] = fb(B[(k0+4)*136 + cn]);
            }
            #pragma unroll
            for (int mf=0; mf<4; mf++)
                #pragma unroll
                for (int nf=0; nf<4; nf++)
                    mma8(acc[mf][nf], af[mf], bf[nf]);
        }
    }

    #pragma unroll
    for (int mf=0; mf<4; mf++){
        int m = m0 + wm + mf*16 + (lane>>2);
        #pragma unroll
        for (int nf=0; nf<4; nf++){
            int n = n0 + wn + nf*8 + (lane&3)*2;
            float2 v0; v0.x = acc[mf][nf][0]; v0.y = acc[mf][nf][1];
            float2 v1; v1.x = acc[mf][nf][2]; v1.y = acc[mf][nf][3];
            *(float2*)(g_PV + (size_t)m*1024 + n)     = v0;
            *(float2*)(g_PV + (size_t)(m+8)*1024 + n) = v1;
        }
    }
}

// ============================================================
// K3: per-batch attention + layernorm. grid 256, 512 thr.
// ============================================================
#define HS_STRIDE 516
#define SMEM3_FLOATS (64*HS_STRIDE + 64*65 + 4096 + 4096 + 128)

extern __shared__ float sm3[];

__global__ __launch_bounds__(512,1) void k_attn(
    const float* __restrict__ h, const float* __restrict__ lng,
    const float* __restrict__ lnb, float* __restrict__ out)
{
    float* hs = sm3;
    float* ls = hs + 64*HS_STRIDE;
    float* ps = ls + 64*65;
    float* qs = ps + 4096;
    float* mean_s = qs + 4096;
    float* rstd_s = mean_s + 64;

    const int b = blockIdx.x;
    const int tid = threadIdx.x, lane = tid&31, wid = tid>>5;
    const float* Pb = g_PV + (size_t)b*64*1024;

    #pragma unroll
    for (int it=0; it<16; it++){
        int idx = tid + it*512;
        int r = idx>>7, c4 = (idx&127)*4;
        *(float4*)&hs[r*HS_STRIDE + c4] = *(const float4*)(h + ((size_t)b*64 + r)*512 + c4);
    }
    __syncthreads();

    {
        const int k0 = (tid>>4)*2, q4 = tid&15;
        float la[2][4];
        #pragma unroll
        for (int i=0;i<2;i++)
            #pragma unroll
            for (int j=0;j<4;j++) la[i][j]=0.f;
        for (int d=0; d<512; d+=4){
            float4 p0 = *(const float4*)(Pb + (size_t)k0*1024 + d);
            float4 p1 = *(const float4*)(Pb + (size_t)(k0+1)*1024 + d);
            #pragma unroll
            for (int j=0;j<4;j++){
                float4 hv = *(const float4*)&hs[(q4 + j*16)*HS_STRIDE + d];
                la[0][j] += p0.x*hv.x + p0.y*hv.y + p0.z*hv.z + p0.w*hv.w;
                la[1][j] += p1.x*hv.x + p1.y*hv.y + p1.z*hv.z + p1.w*hv.w;
            }
        }
        #pragma unroll
        for (int j=0;j<4;j++){
            ls[k0*65 + q4 + j*16]     = la[0][j];
            ls[(k0+1)*65 + q4 + j*16] = la[1][j];
        }
    }
    __syncthreads();

    #pragma unroll
    for (int i=0;i<4;i++){
        int r = wid*4 + i;
        float v0 = ls[r*65 + lane], v1 = ls[r*65 + lane + 32];
        float m = wmax(fmaxf(v0, v1));
        float e0 = __expf(v0 - m), e1 = __expf(v1 - m);
        float inv = 1.f / wsum(e0 + e1);
        ls[r*65 + lane] = e0*inv;
        ls[r*65 + lane + 32] = e1*inv;
    }
    __syncthreads();

    #pragma unroll
    for (int it=0; it<16; it++){
        int idx = tid + it*512;
        int r = idx>>7, c4 = (idx&127)*4;
        *(float4*)&hs[r*HS_STRIDE + c4] = *(const float4*)(Pb + (size_t)r*1024 + 512 + c4);
    }
    __syncthreads();

    const int kg = tid>>6, dg = tid&63;
    float o[8][8];
    #pragma unroll
    for (int i=0;i<8;i++)
        #pragma unroll
        for (int j=0;j<8;j++) o[i][j]=0.f;
    for (int q=0; q<64; q++){
        float pr[8];
        #pragma unroll
        for (int i=0;i<8;i++) pr[i] = ls[(kg*8+i)*65 + q];
        float4 v0 = *(const float4*)&hs[q*HS_STRIDE + dg*8];
        float4 v1 = *(const float4*)&hs[q*HS_STRIDE + dg*8 + 4];
        #pragma unroll
        for (int i=0;i<8;i++){
            o[i][0] += pr[i]*v0.x; o[i][1] += pr[i]*v0.y;
            o[i][2] += pr[i]*v0.z; o[i][3] += pr[i]*v0.w;
            o[i][4] += pr[i]*v1.x; o[i][5] += pr[i]*v1.y;
            o[i][6] += pr[i]*v1.z; o[i][7] += pr[i]*v1.w;
        }
    }

    #pragma unroll
    for (int i=0;i<8;i++){
        float s1=0.f, s2=0.f;
        #pragma unroll
        for (int j=0;j<8;j++){ s1 += o[i][j]; s2 += o[i][j]*o[i][j]; }
        ps[(kg*8+i)*64 + dg] = s1;
        qs[(kg*8+i)*64 + dg] = s2;
    }
    __syncthreads();
    if (tid < 64){
        float s1=0.f, s2=0.f;
        #pragma unroll 8
        for (int g2=0; g2<64; g2++){ s1 += ps[tid*64+g2]; s2 += qs[tid*64+g2]; }
        float mu = s1 * (1.f/512.f);
        float var = s2 * (1.f/512.f) - mu*mu;
        mean_s[tid] = mu;
        rstd_s[tid] = rsqrtf(var + 1e-5f);
    }
    __syncthreads();
    float4 g0 = *(const float4*)(lng + dg*8), g1 = *(const float4*)(lng + dg*8 + 4);
    float4 b0 = *(const float4*)(lnb + dg*8), b1 = *(const float4*)(lnb + dg*8 + 4);
    #pragma unroll
    for (int i=0;i<8;i++){
        int k = kg*8 + i;
        float mu = mean_s[k], rs = rstd_s[k];
        float4 o0, o1;
        o0.x = (o[i][0]-mu)*rs*g0.x + b0.x;  o0.y = (o[i][1]-mu)*rs*g0.y + b0.y;
        o0.z = (o[i][2]-mu)*rs*g0.z + b0.z;  o0.w = (o[i][3]-mu)*rs*g0.w + b0.w;
        o1.x = (o[i][4]-mu)*rs*g1.x + b1.x;  o1.y = (o[i][5]-mu)*rs*g1.y + b1.y;
        o1.z = (o[i][6]-mu)*rs*g1.z + b1.z;  o1.w = (o[i][7]-mu)*rs*g1.w + b1.w;
        float* op = out + ((size_t)b*64 + k)*512 + dg*8;
        *(float4*)op = o0;
        *(float4*)(op+4) = o1;
    }
}

extern "C" void kernel_launch(void* const* d_in, const int* in_sizes, int n_in,
                              void* d_out, int out_size) {
    const float* h   = (const float*)d_in[0];
    const float* z   = (const float*)d_in[1];
    const float* Whk = (const float*)d_in[2];
    const float* Whv = (const float*)d_in[3];
    const float* Wzk = (const float*)d_in[4];
    const float* Wzv = (const float*)d_in[5];
    const float* Wq  = (const float*)d_in[6];
    const float* Wo  = (const float*)d_in[7];
    const float* lng = (const float*)d_in[8];
    const float* lnb = (const float*)d_in[9];
    float* out = (float*)d_out;

    cudaFuncSetAttribute(k_pv, cudaFuncAttributeMaxDynamicSharedMemorySize, KPV_SMEM_BYTES);
    cudaFuncSetAttribute(k_attn, cudaFuncAttributeMaxDynamicSharedMemorySize,
                         SMEM3_FLOATS*(int)sizeof(float));

    k_fuse<<<dim3(8,8,4), 512>>>(Whk, Whv, Wzk, Wzv, Wq, Wo);
    k_pv<<<dim3(8,128), 256, KPV_SMEM_BYTES>>>(h, z);
    k_attn<<<256, 512, SMEM3_FLOATS*sizeof(float)>>>(h, lng, lnb, out);
}

// round 7
// speedup vs baseline: 1.2144x; 1.0088x over previous
#include <cuda_runtime.h>
#include <stdint.h>
#include <math.h>

#define NB 256
#define TOK (NB*64)

// g_Wp[n][pair-packed k]: n = output dim (0-511 logits-proj scaled+tf32, 512-1023 value-proj tf32)
//   pair layout: float2 slot g*4+u = (W[k=g*8+u][n], W[k=g*8+u+4][n]), k = input dim (h 0-511, z 512-1023)
__device__ float g_Wp[1024*1024];
// g_Xp[t][pair-packed k]: same pair layout over k, values tf32-rounded; k 0-511 = h, 512-1023 = z
__device__ float g_Xp[(size_t)TOK*1024];
__device__ float g_PV[(size_t)TOK*1024];

__device__ __forceinline__ float to_tf32(float x){ float r; asm("cvt.rna.tf32.f32 %0, %1;" : "=f"(r) : "f"(x)); return r; }
__device__ __forceinline__ uint32_t fb(float x){ return __float_as_uint(x); }
__device__ __forceinline__ void mma8(float* c, const uint32_t* a, const uint32_t* b){
    asm volatile("mma.sync.aligned.m16n8k8.row.col.f32.tf32.tf32.f32 "
        "{%0,%1,%2,%3}, {%4,%5,%6,%7}, {%8,%9}, {%0,%1,%2,%3};"
        : "+f"(c[0]), "+f"(c[1]), "+f"(c[2]), "+f"(c[3])
        : "r"(a[0]), "r"(a[1]), "r"(a[2]), "r"(a[3]), "r"(b[0]), "r"(b[1]));
}
__device__ __forceinline__ float wmax(float v){
    #pragma unroll
    for (int o=16;o>0;o>>=1) v = fmaxf(v, __shfl_xor_sync(0xffffffffu,v,o));
    return v;
}
__device__ __forceinline__ float wsum(float v){
    #pragma unroll
    for (int o=16;o>0;o>>=1) v += __shfl_xor_sync(0xffffffffu,v,o);
    return v;
}
__device__ __forceinline__ uint32_t smem_u32(const void* p){
    uint32_t a; asm("{ .reg .u64 t; cvta.to.shared.u64 t, %1; cvt.u32.u64 %0, t; }" : "=r"(a) : "l"(p));
    return a;
}
__device__ __forceinline__ void cpa16(uint32_t dst, const void* src){
    asm volatile("cp.async.cg.shared.global [%0], [%1], 16;" :: "r"(dst), "l"(src) : "memory");
}
__device__ __forceinline__ void cpa_commit(){ asm volatile("cp.async.commit_group;" ::: "memory"); }

// ============================================================
// K0: prep — merge h|z, round to tf32, pair-permute into g_Xp.
// One thread per (t, 8-k-group). grid 8192 x 256.
// ============================================================
__global__ __launch_bounds__(256,8) void k_prep(
    const float* __restrict__ h, const float* __restrict__ z)
{
    int idx = blockIdx.x*256 + threadIdx.x;      // 0 .. 16384*128-1
    int t = idx >> 7, g = idx & 127;
    const float* X = (g < 64) ? h : z;
    const float* p = X + (size_t)t*512 + (g & 63)*8;
    float4 v0 = *(const float4*)p;
    float4 v1 = *(const float4*)(p + 4);
    float4 o0, o1;
    o0.x = to_tf32(v0.x); o0.y = to_tf32(v1.x);
    o0.z = to_tf32(v0.y); o0.w = to_tf32(v1.y);
    o1.x = to_tf32(v0.z); o1.y = to_tf32(v1.z);
    o1.z = to_tf32(v0.w); o1.w = to_tf32(v1.w);
    float* dst = g_Xp + (size_t)t*1024 + g*8;
    *(float4*)dst = o0;
    *(float4*)(dst + 4) = o1;
}

// ============================================================
// K1: fused weight precompute via tf32 mma.sync, 3-stage cp.async.
// Template BT: 0 -> quads {Whk^T Wq_h, Wzk^T Wq_z} (scaled, cols 0-511)
//              1 -> quads {Whv^T Wo_h^T, Wzv^T Wo_z^T} (cols 512-1023)
// grid 32 (2 quads x 16 tiles of 128x128), 256 thr, warps 2m x 4n.
// C[m,n] = sum_e A[e,m] * B[e,n]; m = input-dim k, n = output dim.
// Output scattered to g_Wp pair-packed layout, tf32-rounded.
// ============================================================
#define FU_A_FLOATS (32*136)
#define FU_B_FLOATS (128*36)
#define FU_STF      (FU_A_FLOATS + FU_B_FLOATS)
#define FU_SMEM_BYTES (3*FU_STF*4)

extern __shared__ float fusm[];

template<int BT>
__global__ __launch_bounds__(256,1) void k_fuse_tc(
    const float* __restrict__ A0, const float* __restrict__ A1,
    const float* __restrict__ B0, const float* __restrict__ B1)
{
    const int tid = threadIdx.x, lane = tid&31, wid = tid>>5;
    const int q = lane>>2, s = lane&3;
    const int qd = blockIdx.x >> 4;
    const int tile = blockIdx.x & 15;
    const float* Ap = qd ? A1 : A0;
    const float* Bp = qd ? B1 : B0;
    const int row0 = qd*512, col0 = BT*512;
    const float scale = BT ? 1.f : 0.04419417382415922f;
    const int m0 = (tile>>2)*128, n0 = (tile&3)*128;
    const int wm = (wid>>2)*64, wn = (wid&3)*32;

    float* stA[3]; float* stB[3];
    #pragma unroll
    for (int ss=0;ss<3;ss++){ stA[ss] = fusm + ss*FU_STF; stB[ss] = stA[ss] + FU_A_FLOATS; }

    float acc[4][4][4];
    #pragma unroll
    for (int a=0;a<4;a++)
        #pragma unroll
        for (int b=0;b<4;b++)
            #pragma unroll
            for (int c=0;c<4;c++) acc[a][b][c]=0.f;

    auto fill = [&](int c){
        const int si = c%3;
        const int kc = c*32;
        float* A = stA[si]; float* B = stB[si];
        #pragma unroll
        for (int i=0;i<4;i++){           // A: 32 e-rows x 128 m floats, stride 136
            int u = tid + 256*i;
            int e = u>>5, j = u&31;
            cpa16(smem_u32(A + e*136 + j*4), Ap + (size_t)(kc+e)*512 + m0 + j*4);
        }
        if (BT == 0){
            #pragma unroll
            for (int i=0;i<4;i++){       // B: [e][n], stride 136
                int u = tid + 256*i;
                int e = u>>5, j = u&31;
                cpa16(smem_u32(B + e*136 + j*4), Bp + (size_t)(kc+e)*512 + n0 + j*4);
            }
        } else {
            #pragma unroll
            for (int i=0;i<4;i++){       // B: [n][e], stride 36 (rows of Wo, 2048 wide)
                int u = tid + 256*i;
                int n = u>>3, j = u&7;
                cpa16(smem_u32(B + n*36 + j*4), Bp + (size_t)(n0+n)*2048 + kc + j*4);
            }
        }
        cpa_commit();
    };

    fill(0); fill(1);

    for (int c = 0; c < 32; c++){
        if (c < 31) asm volatile("cp.async.wait_group 1;" ::: "memory");
        else        asm volatile("cp.async.wait_group 0;" ::: "memory");
        __syncthreads();
        if (c < 30) fill(c+2);

        const float* A = stA[c%3];
        const float* B = stB[c%3];
        #pragma unroll
        for (int ks=0; ks<4; ks++){
            const int k0 = ks*8 + s;
            uint32_t bf[4][2];
            #pragma unroll
            for (int nf=0; nf<4; nf++){
                int cn = wn + nf*8 + q;
                if (BT == 0){
                    bf[nf][0] = fb(to_tf32(B[k0*136 + cn]));
                    bf[nf][1] = fb(to_tf32(B[(k0+4)*136 + cn]));
                } else {
                    bf[nf][0] = fb(to_tf32(B[cn*36 + k0]));
                    bf[nf][1] = fb(to_tf32(B[cn*36 + k0 + 4]));
                }
            }
            uint32_t af[4][4];
            #pragma unroll
            for (int mf=0; mf<4; mf++){
                int r = wm + mf*16 + q;
                af[mf][0] = fb(to_tf32(A[k0*136 + r]));
                af[mf][1] = fb(to_tf32(A[k0*136 + r + 8]));
                af[mf][2] = fb(to_tf32(A[(k0+4)*136 + r]));
                af[mf][3] = fb(to_tf32(A[(k0+4)*136 + r + 8]));
            }
            #pragma unroll
            for (int mf=0; mf<4; mf++)
                #pragma unroll
                for (int nf=0; nf<4; nf++)
                    mma8(acc[mf][nf], af[mf], bf[nf]);
        }
    }

    // Epilogue: scatter into g_Wp pair-packed layout, tf32-rounded.
    #pragma unroll
    for (int mf=0; mf<4; mf++){
        int M = row0 + m0 + wm + mf*16 + q;
        #pragma unroll
        for (int nf=0; nf<4; nf++){
            int N = col0 + n0 + wn + nf*8 + s*2;
            #pragma unroll
            for (int e=0; e<4; e++){
                int Mx = M + ((e>>1)<<3);
                int Nx = N + (e&1);
                g_Wp[(size_t)Nx*1024 + ((Mx>>3)<<3) + ((Mx&3)<<1) + ((Mx>>2)&1)]
                    = to_tf32(scale*acc[mf][nf][e]);
            }
        }
    }
}

// ============================================================
// K2: PV = X @ Wp^T  (M=16384,N=1024,K=1024), tf32 mma.sync.
// Inputs pre-rounded + pair-packed -> all frag loads are LDS.64,
// no CVT in the mainloop. CTA 128x128, 3-stage cp.async pipeline.
// smem stage: A 128x32 + B 128x32 floats = 32 KB, XOR-swizzled 16B units.
// ============================================================
#define PV_STF 8192
#define PV_SMEM_BYTES (3*PV_STF*4)

extern __shared__ float pvsm[];

__global__ __launch_bounds__(256,2) void k_pv()
{
    const int tid = threadIdx.x, lane = tid&31, wid = tid>>5;
    const int q = lane>>2, s = lane&3;
    const int m0 = blockIdx.y*128, n0 = blockIdx.x*128;
    const int wm = (wid>>2)*64, wn = (wid&3)*32;

    float* stA[3]; float* stB[3];
    #pragma unroll
    for (int ss=0;ss<3;ss++){ stA[ss] = pvsm + ss*PV_STF; stB[ss] = stA[ss] + 4096; }

    // swizzled float2 offsets (in floats) within a 32-float row, per ks
    int poff[4];
    #pragma unroll
    for (int ks=0;ks<4;ks++) poff[ks] = (((ks*2 + (s>>1)) ^ q) << 2) + ((s&1) << 1);

    float acc[4][4][4];
    #pragma unroll
    for (int a=0;a<4;a++)
        #pragma unroll
        for (int b=0;b<4;b++)
            #pragma unroll
            for (int c=0;c<4;c++) acc[a][b][c]=0.f;

    auto fill = [&](int c){
        const int si = c%3;
        float* A = stA[si]; float* B = stB[si];
        #pragma unroll
        for (int i=0;i<4;i++){
            int u = tid + 256*i;
            int r = u>>3, j = u&7;
            cpa16(smem_u32(A + r*32 + ((j ^ (r&7))<<2)),
                  g_Xp + (size_t)(m0+r)*1024 + c*32 + j*4);
        }
        #pragma unroll
        for (int i=0;i<4;i++){
            int u = tid + 256*i;
            int r = u>>3, j = u&7;
            cpa16(smem_u32(B + r*32 + ((j ^ (r&7))<<2)),
                  g_Wp + (size_t)(n0+r)*1024 + c*32 + j*4);
        }
        cpa_commit();
    };

    fill(0); fill(1);

    for (int c = 0; c < 32; c++){
        if (c < 31) asm volatile("cp.async.wait_group 1;" ::: "memory");
        else        asm volatile("cp.async.wait_group 0;" ::: "memory");
        __syncthreads();
        if (c < 30) fill(c+2);

        const float* A = stA[c%3];
        const float* B = stB[c%3];
        #pragma unroll
        for (int ks=0; ks<4; ks++){
            uint32_t bf[4][2];
            #pragma unroll
            for (int nf=0; nf<4; nf++){
                int rb = wn + nf*8 + q;
                float2 v = *(const float2*)(B + rb*32 + poff[ks]);
                bf[nf][0] = fb(v.x); bf[nf][1] = fb(v.y);
            }
            uint32_t af[4][4];
            #pragma unroll
            for (int mf=0; mf<4; mf++){
                int ra = wm + mf*16 + q;
                const float* ap = A + ra*32;
                float2 lo = *(const float2*)(ap + poff[ks]);
                float2 hi = *(const float2*)(ap + 256 + poff[ks]);   // row +8
                af[mf][0] = fb(lo.x); af[mf][1] = fb(hi.x);
                af[mf][2] = fb(lo.y); af[mf][3] = fb(hi.y);
            }
            #pragma unroll
            for (int mf=0; mf<4; mf++)
                #pragma unroll
                for (int nf=0; nf<4; nf++)
                    mma8(acc[mf][nf], af[mf], bf[nf]);
        }
    }

    #pragma unroll
    for (int mf=0; mf<4; mf++){
        int m = m0 + wm + mf*16 + q;
        #pragma unroll
        for (int nf=0; nf<4; nf++){
            int n = n0 + wn + nf*8 + s*2;
            float2 v0; v0.x = acc[mf][nf][0]; v0.y = acc[mf][nf][1];
            float2 v1; v1.x = acc[mf][nf][2]; v1.y = acc[mf][nf][3];
            *(float2*)(g_PV + (size_t)m*1024 + n)     = v0;
            *(float2*)(g_PV + (size_t)(m+8)*1024 + n) = v1;
        }
    }
}

// ============================================================
// K3: per-batch attention + layernorm. grid 256, 512 thr.
// ============================================================
#define HS_STRIDE 516
#define SMEM3_FLOATS (64*HS_STRIDE + 64*65 + 4096 + 4096 + 128)

extern __shared__ float sm3[];

__global__ __launch_bounds__(512,1) void k_attn(
    const float* __restrict__ h, const float* __restrict__ lng,
    const float* __restrict__ lnb, float* __restrict__ out)
{
    float* hs = sm3;
    float* ls = hs + 64*HS_STRIDE;
    float* ps = ls + 64*65;
    float* qs = ps + 4096;
    float* mean_s = qs + 4096;
    float* rstd_s = mean_s + 64;

    const int b = blockIdx.x;
    const int tid = threadIdx.x, lane = tid&31, wid = tid>>5;
    const float* Pb = g_PV + (size_t)b*64*1024;

    #pragma unroll
    for (int it=0; it<16; it++){
        int idx = tid + it*512;
        int r = idx>>7, c4 = (idx&127)*4;
        *(float4*)&hs[r*HS_STRIDE + c4] = *(const float4*)(h + ((size_t)b*64 + r)*512 + c4);
    }
    __syncthreads();

    {
        const int k0 = (tid>>4)*2, q4 = tid&15;
        float la[2][4];
        #pragma unroll
        for (int i=0;i<2;i++)
            #pragma unroll
            for (int j=0;j<4;j++) la[i][j]=0.f;
        for (int d=0; d<512; d+=4){
            float4 p0 = *(const float4*)(Pb + (size_t)k0*1024 + d);
            float4 p1 = *(const float4*)(Pb + (size_t)(k0+1)*1024 + d);
            #pragma unroll
            for (int j=0;j<4;j++){
                float4 hv = *(const float4*)&hs[(q4 + j*16)*HS_STRIDE + d];
                la[0][j] += p0.x*hv.x + p0.y*hv.y + p0.z*hv.z + p0.w*hv.w;
                la[1][j] += p1.x*hv.x + p1.y*hv.y + p1.z*hv.z + p1.w*hv.w;
            }
        }
        #pragma unroll
        for (int j=0;j<4;j++){
            ls[k0*65 + q4 + j*16]     = la[0][j];
            ls[(k0+1)*65 + q4 + j*16] = la[1][j];
        }
    }
    __syncthreads();

    #pragma unroll
    for (int i=0;i<4;i++){
        int r = wid*4 + i;
        float v0 = ls[r*65 + lane], v1 = ls[r*65 + lane + 32];
        float m = wmax(fmaxf(v0, v1));
        float e0 = __expf(v0 - m), e1 = __expf(v1 - m);
        float inv = 1.f / wsum(e0 + e1);
        ls[r*65 + lane] = e0*inv;
        ls[r*65 + lane + 32] = e1*inv;
    }
    __syncthreads();

    #pragma unroll
    for (int it=0; it<16; it++){
        int idx = tid + it*512;
        int r = idx>>7, c4 = (idx&127)*4;
        *(float4*)&hs[r*HS_STRIDE + c4] = *(const float4*)(Pb + (size_t)r*1024 + 512 + c4);
    }
    __syncthreads();

    const int kg = tid>>6, dg = tid&63;
    float o[8][8];
    #pragma unroll
    for (int i=0;i<8;i++)
        #pragma unroll
        for (int j=0;j<8;j++) o[i][j]=0.f;
    for (int q2=0; q2<64; q2++){
        float pr[8];
        #pragma unroll
        for (int i=0;i<8;i++) pr[i] = ls[(kg*8+i)*65 + q2];
        float4 v0 = *(const float4*)&hs[q2*HS_STRIDE + dg*8];
        float4 v1 = *(const float4*)&hs[q2*HS_STRIDE + dg*8 + 4];
        #pragma unroll
        for (int i=0;i<8;i++){
            o[i][0] += pr[i]*v0.x; o[i][1] += pr[i]*v0.y;
            o[i][2] += pr[i]*v0.z; o[i][3] += pr[i]*v0.w;
            o[i][4] += pr[i]*v1.x; o[i][5] += pr[i]*v1.y;
            o[i][6] += pr[i]*v1.z; o[i][7] += pr[i]*v1.w;
        }
    }

    #pragma unroll
    for (int i=0;i<8;i++){
        float s1=0.f, s2=0.f;
        #pragma unroll
        for (int j=0;j<8;j++){ s1 += o[i][j]; s2 += o[i][j]*o[i][j]; }
        ps[(kg*8+i)*64 + dg] = s1;
        qs[(kg*8+i)*64 + dg] = s2;
    }
    __syncthreads();
    if (tid < 64){
        float s1=0.f, s2=0.f;
        #pragma unroll 8
        for (int g2=0; g2<64; g2++){ s1 += ps[tid*64+g2]; s2 += qs[tid*64+g2]; }
        float mu = s1 * (1.f/512.f);
        float var = s2 * (1.f/512.f) - mu*mu;
        mean_s[tid] = mu;
        rstd_s[tid] = rsqrtf(var + 1e-5f);
    }
    __syncthreads();
    float4 g0 = *(const float4*)(lng + dg*8), g1 = *(const float4*)(lng + dg*8 + 4);
    float4 b0 = *(const float4*)(lnb + dg*8), b1 = *(const float4*)(lnb + dg*8 + 4);
    #pragma unroll
    for (int i=0;i<8;i++){
        int k = kg*8 + i;
        float mu = mean_s[k], rs = rstd_s[k];
        float4 o0, o1;
        o0.x = (o[i][0]-mu)*rs*g0.x + b0.x;  o0.y = (o[i][1]-mu)*rs*g0.y + b0.y;
        o0.z = (o[i][2]-mu)*rs*g0.z + b0.z;  o0.w = (o[i][3]-mu)*rs*g0.w + b0.w;
        o1.x = (o[i][4]-mu)*rs*g1.x + b1.x;  o1.y = (o[i][5]-mu)*rs*g1.y + b1.y;
        o1.z = (o[i][6]-mu)*rs*g1.z + b1.z;  o1.w = (o[i][7]-mu)*rs*g1.w + b1.w;
        float* op = out + ((size_t)b*64 + k)*512 + dg*8;
        *(float4*)op = o0;
        *(float4*)(op+4) = o1;
    }
}

extern "C" void kernel_launch(void* const* d_in, const int* in_sizes, int n_in,
                              void* d_out, int out_size) {
    const float* h   = (const float*)d_in[0];
    const float* z   = (const float*)d_in[1];
    const float* Whk = (const float*)d_in[2];
    const float* Whv = (const float*)d_in[3];
    const float* Wzk = (const float*)d_in[4];
    const float* Wzv = (const float*)d_in[5];
    const float* Wq  = (const float*)d_in[6];
    const float* Wo  = (const float*)d_in[7];
    const float* lng = (const float*)d_in[8];
    const float* lnb = (const float*)d_in[9];
    float* out = (float*)d_out;

    cudaFuncSetAttribute(k_fuse_tc<0>, cudaFuncAttributeMaxDynamicSharedMemorySize, FU_SMEM_BYTES);
    cudaFuncSetAttribute(k_fuse_tc<1>, cudaFuncAttributeMaxDynamicSharedMemorySize, FU_SMEM_BYTES);
    cudaFuncSetAttribute(k_pv,   cudaFuncAttributeMaxDynamicSharedMemorySize, PV_SMEM_BYTES);
    cudaFuncSetAttribute(k_attn, cudaFuncAttributeMaxDynamicSharedMemorySize,
                         SMEM3_FLOATS*(int)sizeof(float));

    k_prep<<<8192, 256>>>(h, z);
    k_fuse_tc<0><<<32, 256, FU_SMEM_BYTES>>>(Whk, Wzk, Wq, Wq + 1024*512);
    k_fuse_tc<1><<<32, 256, FU_SMEM_BYTES>>>(Whv, Wzv, Wo, Wo + 1024);
    k_pv<<<dim3(8,128), 256, PV_SMEM_BYTES>>>();
    k_attn<<<256, 512, SMEM3_FLOATS*sizeof(float)>>>(h, lng, lnb, out);
}

// round 8
// speedup vs baseline: 1.3762x; 1.1332x over previous
#include <cuda_runtime.h>
#include <stdint.h>
#include <math.h>

#define NB 256
#define TOK (NB*64)

// g_Wp[n][pair-packed k], g_Xp[t][pair-packed k]: pair layout slot g*4+u = (v[k=g*8+u], v[k=g*8+u+4])
__device__ float g_Wp[1024*1024];
__device__ float g_Xp[(size_t)TOK*1024];
__device__ float g_PV[(size_t)TOK*1024];

__device__ __forceinline__ float to_tf32(float x){ float r; asm("cvt.rna.tf32.f32 %0, %1;" : "=f"(r) : "f"(x)); return r; }
__device__ __forceinline__ uint32_t fb(float x){ return __float_as_uint(x); }
__device__ __forceinline__ void mma8(float* c, const uint32_t* a, const uint32_t* b){
    asm volatile("mma.sync.aligned.m16n8k8.row.col.f32.tf32.tf32.f32 "
        "{%0,%1,%2,%3}, {%4,%5,%6,%7}, {%8,%9}, {%0,%1,%2,%3};"
        : "+f"(c[0]), "+f"(c[1]), "+f"(c[2]), "+f"(c[3])
        : "r"(a[0]), "r"(a[1]), "r"(a[2]), "r"(a[3]), "r"(b[0]), "r"(b[1]));
}
__device__ __forceinline__ float wmax(float v){
    #pragma unroll
    for (int o=16;o>0;o>>=1) v = fmaxf(v, __shfl_xor_sync(0xffffffffu,v,o));
    return v;
}
__device__ __forceinline__ float wsum(float v){
    #pragma unroll
    for (int o=16;o>0;o>>=1) v += __shfl_xor_sync(0xffffffffu,v,o);
    return v;
}
__device__ __forceinline__ uint32_t smem_u32(const void* p){
    uint32_t a; asm("{ .reg .u64 t; cvta.to.shared.u64 t, %1; cvt.u32.u64 %0, t; }" : "=r"(a) : "l"(p));
    return a;
}
__device__ __forceinline__ void cpa16(uint32_t dst, const void* src){
    asm volatile("cp.async.cg.shared.global [%0], [%1], 16;" :: "r"(dst), "l"(src) : "memory");
}
__device__ __forceinline__ void cpa_commit(){ asm volatile("cp.async.commit_group;" ::: "memory"); }

// ============================================================
// K0: prep — merge h|z, tf32-round, pair-permute into g_Xp.
// ============================================================
__global__ __launch_bounds__(256,8) void k_prep(
    const float* __restrict__ h, const float* __restrict__ z)
{
    int idx = blockIdx.x*256 + threadIdx.x;
    int t = idx >> 7, g = idx & 127;
    const float* X = (g < 64) ? h : z;
    const float* p = X + (size_t)t*512 + (g & 63)*8;
    float4 v0 = *(const float4*)p;
    float4 v1 = *(const float4*)(p + 4);
    float4 o0, o1;
    o0.x = to_tf32(v0.x); o0.y = to_tf32(v1.x);
    o0.z = to_tf32(v0.y); o0.w = to_tf32(v1.y);
    o1.x = to_tf32(v0.z); o1.y = to_tf32(v1.z);
    o1.z = to_tf32(v0.w); o1.w = to_tf32(v1.w);
    float* dst = g_Xp + (size_t)t*1024 + g*8;
    *(float4*)dst = o0;
    *(float4*)(dst + 4) = o1;
}

// ============================================================
// K1: fused weight precompute, tf32 mma, merged (runtime BT).
// grid 64 = BT(2) x qd(2) x tile(16). 256 thr.
// ============================================================
#define FU_A_FLOATS (32*136)
#define FU_B_FLOATS (128*36)
#define FU_STF      (FU_A_FLOATS + FU_B_FLOATS)
#define FU_SMEM_BYTES (3*FU_STF*4)

extern __shared__ float fusm[];

__global__ __launch_bounds__(256,1) void k_fuse_tc(
    const float* __restrict__ Whk, const float* __restrict__ Wzk,
    const float* __restrict__ Whv, const float* __restrict__ Wzv,
    const float* __restrict__ Wq,  const float* __restrict__ Wo)
{
    const int tid = threadIdx.x, lane = tid&31, wid = tid>>5;
    const int q = lane>>2, s = lane&3;
    const int BT = blockIdx.x >> 5;
    const int qd = (blockIdx.x >> 4) & 1;
    const int tile = blockIdx.x & 15;
    const float* Ap; const float* Bp;
    if (BT == 0){ Ap = qd ? Wzk : Whk; Bp = qd ? (Wq + 1024*512) : Wq; }
    else        { Ap = qd ? Wzv : Whv; Bp = qd ? (Wo + 1024) : Wo; }
    const int row0 = qd*512, col0 = BT*512;
    const float scale = BT ? 1.f : 0.04419417382415922f;
    const int m0 = (tile>>2)*128, n0 = (tile&3)*128;
    const int wm = (wid>>2)*64, wn = (wid&3)*32;

    float* stA[3]; float* stB[3];
    #pragma unroll
    for (int ss=0;ss<3;ss++){ stA[ss] = fusm + ss*FU_STF; stB[ss] = stA[ss] + FU_A_FLOATS; }

    float acc[4][4][4];
    #pragma unroll
    for (int a=0;a<4;a++)
        #pragma unroll
        for (int b=0;b<4;b++)
            #pragma unroll
            for (int c=0;c<4;c++) acc[a][b][c]=0.f;

    auto fill = [&](int c){
        const int si = c%3;
        const int kc = c*32;
        float* A = stA[si]; float* B = stB[si];
        #pragma unroll
        for (int i=0;i<4;i++){
            int u = tid + 256*i;
            int e = u>>5, j = u&31;
            cpa16(smem_u32(A + e*136 + j*4), Ap + (size_t)(kc+e)*512 + m0 + j*4);
        }
        if (BT == 0){
            #pragma unroll
            for (int i=0;i<4;i++){
                int u = tid + 256*i;
                int e = u>>5, j = u&31;
                cpa16(smem_u32(B + e*136 + j*4), Bp + (size_t)(kc+e)*512 + n0 + j*4);
            }
        } else {
            #pragma unroll
            for (int i=0;i<4;i++){
                int u = tid + 256*i;
                int n = u>>3, j = u&7;
                cpa16(smem_u32(B + n*36 + j*4), Bp + (size_t)(n0+n)*2048 + kc + j*4);
            }
        }
        cpa_commit();
    };

    fill(0); fill(1);

    for (int c = 0; c < 32; c++){
        if (c < 31) asm volatile("cp.async.wait_group 1;" ::: "memory");
        else        asm volatile("cp.async.wait_group 0;" ::: "memory");
        __syncthreads();
        if (c < 30) fill(c+2);

        const float* A = stA[c%3];
        const float* B = stB[c%3];
        #pragma unroll
        for (int ks=0; ks<4; ks++){
            const int k0 = ks*8 + s;
            uint32_t bf[4][2];
            #pragma unroll
            for (int nf=0; nf<4; nf++){
                int cn = wn + nf*8 + q;
                if (BT == 0){
                    bf[nf][0] = fb(to_tf32(B[k0*136 + cn]));
                    bf[nf][1] = fb(to_tf32(B[(k0+4)*136 + cn]));
                } else {
                    bf[nf][0] = fb(to_tf32(B[cn*36 + k0]));
                    bf[nf][1] = fb(to_tf32(B[cn*36 + k0 + 4]));
                }
            }
            uint32_t af[4][4];
            #pragma unroll
            for (int mf=0; mf<4; mf++){
                int r = wm + mf*16 + q;
                af[mf][0] = fb(to_tf32(A[k0*136 + r]));
                af[mf][1] = fb(to_tf32(A[k0*136 + r + 8]));
                af[mf][2] = fb(to_tf32(A[(k0+4)*136 + r]));
                af[mf][3] = fb(to_tf32(A[(k0+4)*136 + r + 8]));
            }
            #pragma unroll
            for (int mf=0; mf<4; mf++)
                #pragma unroll
                for (int nf=0; nf<4; nf++)
                    mma8(acc[mf][nf], af[mf], bf[nf]);
        }
    }

    #pragma unroll
    for (int mf=0; mf<4; mf++){
        int M = row0 + m0 + wm + mf*16 + q;
        #pragma unroll
        for (int nf=0; nf<4; nf++){
            int N = col0 + n0 + wn + nf*8 + s*2;
            #pragma unroll
            for (int e=0; e<4; e++){
                int Mx = M + ((e>>1)<<3);
                int Nx = N + (e&1);
                g_Wp[(size_t)Nx*1024 + ((Mx>>3)<<3) + ((Mx&3)<<1) + ((Mx>>2)&1)]
                    = to_tf32(scale*acc[mf][nf][e]);
            }
        }
    }
}

// ============================================================
// K2: PV = X @ Wp^T, tf32 mma. CTA 128m x 256n, warp tile 64x64,
// 3-stage cp.async. grid (4,128), 256 thr, 1 CTA/SM.
// stage: A 128x32 + B 256x32 floats = 48 KB.
// ============================================================
#define PV_STF (128*32 + 256*32)
#define PV_SMEM_BYTES (3*PV_STF*4)

extern __shared__ float pvsm[];

__global__ __launch_bounds__(256,1) void k_pv()
{
    const int tid = threadIdx.x, lane = tid&31, wid = tid>>5;
    const int q = lane>>2, s = lane&3;
    const int m0 = blockIdx.y*128, n0 = blockIdx.x*256;
    const int wm = (wid>>2)*64, wn = (wid&3)*64;

    float* stA[3]; float* stB[3];
    #pragma unroll
    for (int ss=0;ss<3;ss++){ stA[ss] = pvsm + ss*PV_STF; stB[ss] = stA[ss] + 128*32; }

    int poff[4];
    #pragma unroll
    for (int ks=0;ks<4;ks++) poff[ks] = (((ks*2 + (s>>1)) ^ q) << 2) + ((s&1) << 1);

    float acc[4][8][4];
    #pragma unroll
    for (int a=0;a<4;a++)
        #pragma unroll
        for (int b=0;b<8;b++)
            #pragma unroll
            for (int c=0;c<4;c++) acc[a][b][c]=0.f;

    auto fill = [&](int c){
        const int si = c%3;
        float* A = stA[si]; float* B = stB[si];
        #pragma unroll
        for (int i=0;i<4;i++){
            int u = tid + 256*i;
            int r = u>>3, j = u&7;
            cpa16(smem_u32(A + r*32 + ((j ^ (r&7))<<2)),
                  g_Xp + (size_t)(m0+r)*1024 + c*32 + j*4);
        }
        #pragma unroll
        for (int i=0;i<8;i++){
            int u = tid + 256*i;
            int r = u>>3, j = u&7;
            cpa16(smem_u32(B + r*32 + ((j ^ (r&7))<<2)),
                  g_Wp + (size_t)(n0+r)*1024 + c*32 + j*4);
        }
        cpa_commit();
    };

    fill(0); fill(1);

    for (int c = 0; c < 32; c++){
        if (c < 31) asm volatile("cp.async.wait_group 1;" ::: "memory");
        else        asm volatile("cp.async.wait_group 0;" ::: "memory");
        __syncthreads();
        if (c < 30) fill(c+2);

        const float* A = stA[c%3];
        const float* B = stB[c%3];
        #pragma unroll
        for (int ks=0; ks<4; ks++){
            uint32_t bf[8][2];
            #pragma unroll
            for (int nf=0; nf<8; nf++){
                int rb = wn + nf*8 + q;
                float2 v = *(const float2*)(B + rb*32 + poff[ks]);
                bf[nf][0] = fb(v.x); bf[nf][1] = fb(v.y);
            }
            uint32_t af[4][4];
            #pragma unroll
            for (int mf=0; mf<4; mf++){
                int ra = wm + mf*16 + q;
                const float* ap = A + ra*32;
                float2 lo = *(const float2*)(ap + poff[ks]);
                float2 hi = *(const float2*)(ap + 256 + poff[ks]);
                af[mf][0] = fb(lo.x); af[mf][1] = fb(hi.x);
                af[mf][2] = fb(lo.y); af[mf][3] = fb(hi.y);
            }
            #pragma unroll
            for (int mf=0; mf<4; mf++)
                #pragma unroll
                for (int nf=0; nf<8; nf++)
                    mma8(acc[mf][nf], af[mf], bf[nf]);
        }
    }

    #pragma unroll
    for (int mf=0; mf<4; mf++){
        int m = m0 + wm + mf*16 + q;
        #pragma unroll
        for (int nf=0; nf<8; nf++){
            int n = n0 + wn + nf*8 + s*2;
            float2 v0; v0.x = acc[mf][nf][0]; v0.y = acc[mf][nf][1];
            float2 v1; v1.x = acc[mf][nf][2]; v1.y = acc[mf][nf][3];
            *(float2*)(g_PV + (size_t)m*1024 + n)     = v0;
            *(float2*)(g_PV + (size_t)(m+8)*1024 + n) = v1;
        }
    }
}

// ============================================================
// K3: per-batch attention + LN on tensor pipe. grid 256, 512 thr.
// smem (floats): ls[64][68], gs[512], bs[512],
//   overlay: {Pc[64][132], hc[64][132]} / {Vt[128][68], Ob[64][516]}
// ============================================================
#define AT_LS   0
#define AT_GS   (64*68)
#define AT_BS   (AT_GS + 512)
#define AT_OV   (AT_BS + 512)
#define AT_SMEM_FLOATS (AT_OV + 8704 + 64*516)
#define AT_SMEM_BYTES  (AT_SMEM_FLOATS*4)

extern __shared__ float atsm[];

__global__ __launch_bounds__(512,1) void k_attn_tc(
    const float* __restrict__ h, const float* __restrict__ lng,
    const float* __restrict__ lnb, float* __restrict__ out)
{
    float* ls = atsm + AT_LS;
    float* gs = atsm + AT_GS;
    float* bs = atsm + AT_BS;
    float* Pc = atsm + AT_OV;          // phase 1
    float* hc = Pc + 64*132;           // phase 1
    float* Vt = atsm + AT_OV;          // phase 2 (overlays Pc)
    float* Ob = Vt + 128*68;           // phase 2

    const int b = blockIdx.x;
    const int tid = threadIdx.x, lane = tid&31, wid = tid>>5;
    const int g = lane>>2, t = lane&3;
    const float* Pb = g_PV + (size_t)b*64*1024;
    const float* hb = h + (size_t)b*64*512;

    gs[tid] = lng[tid];
    bs[tid] = lnb[tid];

    // ---- Phase 1: logits = P @ h^T (tf32 mma), chunked over d ----
    const int wlm = (wid&3)*16, wln = (wid>>2)*16;
    float lacc[2][4];
    #pragma unroll
    for (int i=0;i<2;i++)
        #pragma unroll
        for (int j=0;j<4;j++) lacc[i][j]=0.f;

    for (int dc=0; dc<4; dc++){
        #pragma unroll
        for (int it=0; it<4; it++){
            int v = tid + it*512;
            int qq = v>>5, f4 = (v&31)*4;
            float4 pv = *(const float4*)(Pb + (size_t)qq*1024 + dc*128 + f4);
            float4 cv; cv.x=to_tf32(pv.x); cv.y=to_tf32(pv.y); cv.z=to_tf32(pv.z); cv.w=to_tf32(pv.w);
            *(float4*)(Pc + qq*132 + f4) = cv;
            float4 hv = *(const float4*)(hb + (size_t)qq*512 + dc*128 + f4);
            float4 ch; ch.x=to_tf32(hv.x); ch.y=to_tf32(hv.y); ch.z=to_tf32(hv.z); ch.w=to_tf32(hv.w);
            *(float4*)(hc + qq*132 + f4) = ch;
        }
        __syncthreads();
        #pragma unroll
        for (int kk=0; kk<16; kk++){
            uint32_t af[4];
            af[0] = fb(Pc[(wlm+g)*132 + kk*8 + t]);
            af[1] = fb(Pc[(wlm+g+8)*132 + kk*8 + t]);
            af[2] = fb(Pc[(wlm+g)*132 + kk*8 + t + 4]);
            af[3] = fb(Pc[(wlm+g+8)*132 + kk*8 + t + 4]);
            #pragma unroll
            for (int nf=0; nf<2; nf++){
                uint32_t bf[2];
                bf[0] = fb(hc[(wln+nf*8+g)*132 + kk*8 + t]);
                bf[1] = fb(hc[(wln+nf*8+g)*132 + kk*8 + t + 4]);
                mma8(lacc[nf], af, bf);
            }
        }
        __syncthreads();
    }
    #pragma unroll
    for (int nf=0; nf<2; nf++){
        int col = wln + nf*8 + 2*t;
        float2 v0; v0.x = lacc[nf][0]; v0.y = lacc[nf][1];
        float2 v1; v1.x = lacc[nf][2]; v1.y = lacc[nf][3];
        *(float2*)(ls + (wlm+g)*68 + col)   = v0;
        *(float2*)(ls + (wlm+g+8)*68 + col) = v1;
    }
    __syncthreads();

    // ---- Softmax over q (16 warps x 4 rows) ----
    #pragma unroll
    for (int i=0;i<4;i++){
        int r = wid*4 + i;
        float v0 = ls[r*68 + lane], v1 = ls[r*68 + lane + 32];
        float m = wmax(fmaxf(v0, v1));
        float e0 = __expf(v0 - m), e1 = __expf(v1 - m);
        float inv = 1.f / wsum(e0 + e1);
        ls[r*68 + lane] = e0*inv;
        ls[r*68 + lane + 32] = e1*inv;
    }
    __syncthreads();

    // ---- Phase 2: O = probs @ V' (tf32 mma), chunked over d ----
    const int wk = wid>>2, wd = wid&3;
    for (int dc=0; dc<4; dc++){
        #pragma unroll
        for (int it=0; it<4; it++){
            int v = tid + it*512;
            int qq = v & 63, fg = (v>>6)*4;
            float4 vv = *(const float4*)(Pb + (size_t)qq*1024 + 512 + dc*128 + fg);
            Vt[(fg+0)*68 + qq] = to_tf32(vv.x);
            Vt[(fg+1)*68 + qq] = to_tf32(vv.y);
            Vt[(fg+2)*68 + qq] = to_tf32(vv.z);
            Vt[(fg+3)*68 + qq] = to_tf32(vv.w);
        }
        __syncthreads();
        float oc[4][4];
        #pragma unroll
        for (int i=0;i<4;i++)
            #pragma unroll
            for (int j=0;j<4;j++) oc[i][j]=0.f;
        #pragma unroll
        for (int kk=0; kk<8; kk++){
            uint32_t af[4];
            af[0] = fb(ls[(wk*16+g)*68 + kk*8 + t]);
            af[1] = fb(ls[(wk*16+g+8)*68 + kk*8 + t]);
            af[2] = fb(ls[(wk*16+g)*68 + kk*8 + t + 4]);
            af[3] = fb(ls[(wk*16+g+8)*68 + kk*8 + t + 4]);
            #pragma unroll
            for (int nf=0; nf<4; nf++){
                uint32_t bf[2];
                bf[0] = fb(Vt[(wd*32+nf*8+g)*68 + kk*8 + t]);
                bf[1] = fb(Vt[(wd*32+nf*8+g)*68 + kk*8 + t + 4]);
                mma8(oc[nf], af, bf);
            }
        }
        #pragma unroll
        for (int nf=0; nf<4; nf++){
            int col = dc*128 + wd*32 + nf*8 + 2*t;
            float2 v0; v0.x = oc[nf][0]; v0.y = oc[nf][1];
            float2 v1; v1.x = oc[nf][2]; v1.y = oc[nf][3];
            *(float2*)(Ob + (wk*16+g)*516 + col)   = v0;
            *(float2*)(Ob + (wk*16+g+8)*516 + col) = v1;
        }
        __syncthreads();
    }

    // ---- LayerNorm + write ----
    {
        int row = tid>>3, j = tid&7;
        const float* orow = Ob + row*516 + j*64;
        float s1=0.f, s2=0.f;
        #pragma unroll
        for (int i2=0;i2<64;i2+=4){
            float4 v = *(const float4*)(orow+i2);
            s1 += v.x+v.y+v.z+v.w;
            s2 += v.x*v.x+v.y*v.y+v.z*v.z+v.w*v.w;
        }
        #pragma unroll
        for (int o=1;o<8;o<<=1){
            s1 += __shfl_xor_sync(0xffffffffu, s1, o);
            s2 += __shfl_xor_sync(0xffffffffu, s2, o);
        }
        float mu = s1 * (1.f/512.f);
        float var = s2 * (1.f/512.f) - mu*mu;
        float rs = rsqrtf(var + 1e-5f);
        float* op = out + ((size_t)b*64 + row)*512 + j*64;
        #pragma unroll
        for (int i2=0;i2<64;i2+=4){
            float4 v = *(const float4*)(orow+i2);
            float4 gg = *(const float4*)(gs + j*64 + i2);
            float4 bb = *(const float4*)(bs + j*64 + i2);
            float4 r;
            r.x = (v.x-mu)*rs*gg.x + bb.x;
            r.y = (v.y-mu)*rs*gg.y + bb.y;
            r.z = (v.z-mu)*rs*gg.z + bb.z;
            r.w = (v.w-mu)*rs*gg.w + bb.w;
            *(float4*)(op+i2) = r;
        }
    }
}

extern "C" void kernel_launch(void* const* d_in, const int* in_sizes, int n_in,
                              void* d_out, int out_size) {
    const float* h   = (const float*)d_in[0];
    const float* z   = (const float*)d_in[1];
    const float* Whk = (const float*)d_in[2];
    const float* Whv = (const float*)d_in[3];
    const float* Wzk = (const float*)d_in[4];
    const float* Wzv = (const float*)d_in[5];
    const float* Wq  = (const float*)d_in[6];
    const float* Wo  = (const float*)d_in[7];
    const float* lng = (const float*)d_in[8];
    const float* lnb = (const float*)d_in[9];
    float* out = (float*)d_out;

    cudaFuncSetAttribute(k_fuse_tc, cudaFuncAttributeMaxDynamicSharedMemorySize, FU_SMEM_BYTES);
    cudaFuncSetAttribute(k_pv,      cudaFuncAttributeMaxDynamicSharedMemorySize, PV_SMEM_BYTES);
    cudaFuncSetAttribute(k_attn_tc, cudaFuncAttributeMaxDynamicSharedMemorySize, AT_SMEM_BYTES);

    k_prep<<<8192, 256>>>(h, z);
    k_fuse_tc<<<64, 256, FU_SMEM_BYTES>>>(Whk, Wzk, Whv, Wzv, Wq, Wo);
    k_pv<<<dim3(4,128), 256, PV_SMEM_BYTES>>>();
    k_attn_tc<<<256, 512, AT_SMEM_BYTES>>>(h, lng, lnb, out);
}